// round 1
// baseline (speedup 1.0000x reference)
#include <cuda_runtime.h>

#define SEQ   256
#define LAB   128
#define BATCH 8192
#define NF    8
#define HD    64
#define G3    192
#define TB    64
#define NTHR  512

// Dynamic SMEM layout (float offsets)
//  wih_t  [8][192]      @ 0       (1536)
//  whh_t  [64][192]     @ 1536    (12288)
//  bih    [192]         @ 13824
//  bhh    [192]         @ 14016
//  woutT  [64][8]       @ 14208   (512)
//  bout   [8]           @ 14720
//  xin    [2][512]      @ 14728   (1024)
//  h      [2][64][65]   @ 15752   (8320)   (pad 65 kills bank conflicts in out-proj)
#define OFF_WIH   0
#define OFF_WHH   1536
#define OFF_BIH   13824
#define OFF_BHH   14016
#define OFF_WOUT  14208
#define OFF_BOUT  14720
#define OFF_XIN   14728
#define OFF_H     15752
#define HSTRIDE   65
#define HBUF      (64 * HSTRIDE)
#define SMEM_FLOATS (OFF_H + 2 * HBUF)
#define SMEM_BYTES  (SMEM_FLOATS * sizeof(float))

__device__ __forceinline__ float sigf(float x) {
    return __fdividef(1.0f, 1.0f + __expf(-x));
}
__device__ __forceinline__ float tanhfast(float x) {
    return __fdividef(2.0f, 1.0f + __expf(-2.0f * x)) - 1.0f;
}

__global__ __launch_bounds__(NTHR, 1)
void seq2seq_gru_kernel(const float* __restrict__ x,
                        const float* __restrict__ xy,
                        const float* __restrict__ eWih, const float* __restrict__ eWhh,
                        const float* __restrict__ ebih, const float* __restrict__ ebhh,
                        const float* __restrict__ dWih, const float* __restrict__ dWhh,
                        const float* __restrict__ dbih, const float* __restrict__ dbhh,
                        const float* __restrict__ Wout, const float* __restrict__ bout,
                        float* __restrict__ out)
{
    extern __shared__ float smem[];
    float* wih   = smem + OFF_WIH;    // transposed [k][192]
    float* whh   = smem + OFF_WHH;    // transposed [k][192]
    float* bih   = smem + OFF_BIH;
    float* bhh   = smem + OFF_BHH;
    float* woutT = smem + OFF_WOUT;   // [k][8]
    float* bo    = smem + OFF_BOUT;
    float* xin   = smem + OFF_XIN;    // [2][512]
    float* hbuf  = smem + OFF_H;      // [2][64][65]

    const int tid = threadIdx.x;
    const int j2  = tid & 31;         // hidden-unit lane (owns j2 and j2+32)
    const int rg  = tid >> 5;         // row group 0..15
    const int r0  = rg * 4;           // 4 rows per thread
    const int rowbase = blockIdx.x * TB;

    // ---- load encoder weights (transposed) + zero h ----
    for (int i = tid; i < NF * G3; i += NTHR) {
        int k = i / G3, g = i % G3;
        wih[i] = eWih[g * NF + k];
    }
    for (int i = tid; i < HD * G3; i += NTHR) {
        int k = i / G3, g = i % G3;
        whh[i] = eWhh[g * HD + k];
    }
    for (int i = tid; i < G3; i += NTHR) { bih[i] = ebih[i]; bhh[i] = ebhh[i]; }
    for (int i = tid; i < HBUF; i += NTHR) hbuf[i] = 0.0f;   // h0 = 0 (buffer 0)
    __syncthreads();

    float binr[2], binz[2], binn[2], binh[2];
    #pragma unroll
    for (int p = 0; p < 2; p++) {
        int j = j2 + 32 * p;
        binr[p] = bih[j]        + bhh[j];
        binz[p] = bih[64 + j]   + bhh[64 + j];
        binn[p] = bih[128 + j];
        binh[p] = bhh[128 + j];
    }

    int cur = 0;

    // =========================== ENCODER ===========================
    for (int t = 0; t < SEQ; t++) {
        const int xb = t & 1;
        // stage x_t tile (coalesced: 512 contiguous floats)
        xin[xb * 512 + tid] = x[((size_t)t * BATCH + rowbase) * NF + tid];
        __syncthreads();   // xin ready; prev step's h writes ordered

        float ar[4][2], az[4][2], an[4][2], ah[4][2];
        #pragma unroll
        for (int r = 0; r < 4; r++)
            #pragma unroll
            for (int p = 0; p < 2; p++) {
                ar[r][p] = binr[p]; az[r][p] = binz[p];
                an[r][p] = binn[p]; ah[r][p] = binh[p];
            }

        // input GEMM (k = 0..7)
        const float* xi = &xin[xb * 512];
        #pragma unroll
        for (int k = 0; k < NF; k++) {
            float xv[4];
            #pragma unroll
            for (int r = 0; r < 4; r++) xv[r] = xi[(r0 + r) * NF + k];
            const float* w = &wih[k * G3];
            #pragma unroll
            for (int p = 0; p < 2; p++) {
                int j = j2 + 32 * p;
                float w0 = w[j], w1 = w[64 + j], w2 = w[128 + j];
                #pragma unroll
                for (int r = 0; r < 4; r++) {
                    ar[r][p] += xv[r] * w0;
                    az[r][p] += xv[r] * w1;
                    an[r][p] += xv[r] * w2;
                }
            }
        }

        // recurrent GEMM (k = 0..63)
        const float* hc = &hbuf[cur * HBUF];
        float*       hn = &hbuf[(cur ^ 1) * HBUF];
        #pragma unroll 8
        for (int k = 0; k < HD; k++) {
            float hv[4];
            #pragma unroll
            for (int r = 0; r < 4; r++) hv[r] = hc[(r0 + r) * HSTRIDE + k];
            const float* w = &whh[k * G3];
            #pragma unroll
            for (int p = 0; p < 2; p++) {
                int j = j2 + 32 * p;
                float w0 = w[j], w1 = w[64 + j], w2 = w[128 + j];
                #pragma unroll
                for (int r = 0; r < 4; r++) {
                    ar[r][p] += hv[r] * w0;
                    az[r][p] += hv[r] * w1;
                    ah[r][p] += hv[r] * w2;
                }
            }
        }

        // gates + h update
        #pragma unroll
        for (int r = 0; r < 4; r++) {
            int row = r0 + r;
            #pragma unroll
            for (int p = 0; p < 2; p++) {
                int j = j2 + 32 * p;
                float rr = sigf(ar[r][p]);
                float zz = sigf(az[r][p]);
                float nn = tanhfast(an[r][p] + rr * ah[r][p]);
                float ho = hc[row * HSTRIDE + j];
                hn[row * HSTRIDE + j] = nn + zz * (ho - nn);
            }
        }
        cur ^= 1;
    }
    __syncthreads();   // drain last encoder step before weight overwrite

    // ---- swap in decoder weights + output projection ----
    for (int i = tid; i < NF * G3; i += NTHR) {
        int k = i / G3, g = i % G3;
        wih[i] = dWih[g * NF + k];
    }
    for (int i = tid; i < HD * G3; i += NTHR) {
        int k = i / G3, g = i % G3;
        whh[i] = dWhh[g * HD + k];
    }
    for (int i = tid; i < G3; i += NTHR) { bih[i] = dbih[i]; bhh[i] = dbhh[i]; }
    for (int i = tid; i < HD * NF; i += NTHR) {
        int k = i / NF, o = i % NF;
        woutT[i] = Wout[o * HD + k];
    }
    if (tid < NF) bo[tid] = bout[tid];
    // first decoder input = xy[0]
    xin[tid] = xy[(size_t)rowbase * NF + tid];
    __syncthreads();

    #pragma unroll
    for (int p = 0; p < 2; p++) {
        int j = j2 + 32 * p;
        binr[p] = bih[j]        + bhh[j];
        binz[p] = bih[64 + j]   + bhh[64 + j];
        binn[p] = bih[128 + j];
        binh[p] = bhh[128 + j];
    }

    const int orow = tid >> 3;       // out-projection mapping
    const int oo   = tid & 7;

    // =========================== DECODER ===========================
    for (int t = 0; t < LAB; t++) {
        const int xb = t & 1;

        float ar[4][2], az[4][2], an[4][2], ah[4][2];
        #pragma unroll
        for (int r = 0; r < 4; r++)
            #pragma unroll
            for (int p = 0; p < 2; p++) {
                ar[r][p] = binr[p]; az[r][p] = binz[p];
                an[r][p] = binn[p]; ah[r][p] = binh[p];
            }

        const float* xi = &xin[xb * 512];
        #pragma unroll
        for (int k = 0; k < NF; k++) {
            float xv[4];
            #pragma unroll
            for (int r = 0; r < 4; r++) xv[r] = xi[(r0 + r) * NF + k];
            const float* w = &wih[k * G3];
            #pragma unroll
            for (int p = 0; p < 2; p++) {
                int j = j2 + 32 * p;
                float w0 = w[j], w1 = w[64 + j], w2 = w[128 + j];
                #pragma unroll
                for (int r = 0; r < 4; r++) {
                    ar[r][p] += xv[r] * w0;
                    az[r][p] += xv[r] * w1;
                    an[r][p] += xv[r] * w2;
                }
            }
        }

        const float* hc = &hbuf[cur * HBUF];
        float*       hn = &hbuf[(cur ^ 1) * HBUF];
        #pragma unroll 8
        for (int k = 0; k < HD; k++) {
            float hv[4];
            #pragma unroll
            for (int r = 0; r < 4; r++) hv[r] = hc[(r0 + r) * HSTRIDE + k];
            const float* w = &whh[k * G3];
            #pragma unroll
            for (int p = 0; p < 2; p++) {
                int j = j2 + 32 * p;
                float w0 = w[j], w1 = w[64 + j], w2 = w[128 + j];
                #pragma unroll
                for (int r = 0; r < 4; r++) {
                    ar[r][p] += hv[r] * w0;
                    az[r][p] += hv[r] * w1;
                    ah[r][p] += hv[r] * w2;
                }
            }
        }

        #pragma unroll
        for (int r = 0; r < 4; r++) {
            int row = r0 + r;
            #pragma unroll
            for (int p = 0; p < 2; p++) {
                int j = j2 + 32 * p;
                float rr = sigf(ar[r][p]);
                float zz = sigf(az[r][p]);
                float nn = tanhfast(an[r][p] + rr * ah[r][p]);
                float ho = hc[row * HSTRIDE + j];
                hn[row * HSTRIDE + j] = nn + zz * (ho - nn);
            }
        }
        __syncthreads();   // h_new complete before out projection

        // out = h_new @ Wout^T + bout ; feeds next step + global write
        float acc = bo[oo];
        const float* hnp = hn + orow * HSTRIDE;
        #pragma unroll 8
        for (int k = 0; k < HD; k++) acc += hnp[k] * woutT[k * NF + oo];

        out[((size_t)t * BATCH + rowbase) * NF + tid] = acc;  // coalesced
        xin[(xb ^ 1) * 512 + tid] = acc;

        cur ^= 1;
        __syncthreads();   // xin ready for next step
    }
}

extern "C" void kernel_launch(void* const* d_in, const int* in_sizes, int n_in,
                              void* d_out, int out_size) {
    (void)in_sizes; (void)n_in; (void)out_size;
    const float* x     = (const float*)d_in[0];
    const float* xy    = (const float*)d_in[1];
    const float* eWih  = (const float*)d_in[2];
    const float* eWhh  = (const float*)d_in[3];
    const float* ebih  = (const float*)d_in[4];
    const float* ebhh  = (const float*)d_in[5];
    const float* dWih  = (const float*)d_in[6];
    const float* dWhh  = (const float*)d_in[7];
    const float* dbih  = (const float*)d_in[8];
    const float* dbhh  = (const float*)d_in[9];
    const float* Wout  = (const float*)d_in[10];
    const float* bout  = (const float*)d_in[11];
    float* out = (float*)d_out;

    cudaFuncSetAttribute(seq2seq_gru_kernel,
                         cudaFuncAttributeMaxDynamicSharedMemorySize, SMEM_BYTES);
    seq2seq_gru_kernel<<<BATCH / TB, NTHR, SMEM_BYTES>>>(
        x, xy, eWih, eWhh, ebih, ebhh, dWih, dWhh, dbih, dbhh, Wout, bout, out);
}

// round 2
// speedup vs baseline: 1.3077x; 1.3077x over previous
#include <cuda_runtime.h>

#define SEQ   256
#define LAB   128
#define BATCH 8192
#define NF    8
#define HD    64
#define G3    192
#define NTHR  256          // 8 warps
#define NW    8
#define RPW   8            // rows per warp
#define TB    (NW * RPW)   // 64 rows per block
#define NBLK  (BATCH / TB) // 128 blocks
#define HSTR  68           // h row stride (floats), 16B-aligned, conflict-free in out-proj

// ---- SMEM layout (float offsets) ----
#define OFF_EWIH  0                         // [8][192]
#define OFF_EWHH  (OFF_EWIH + NF*G3)        // [64][192]
#define OFF_DWIH  (OFF_EWHH + HD*G3)
#define OFF_DWHH  (OFF_DWIH + NF*G3)
#define OFF_EB    (OFF_DWHH + HD*G3)        // [4][64]  r, z, n_i, n_h
#define OFF_DB    (OFF_EB + 4*HD)
#define OFF_WOUTP (OFF_DB + 4*HD)           // [64][4][2] pair (Wout[o4][k], Wout[o4+4][k])
#define OFF_BOUTP (OFF_WOUTP + HD*8)        // [4][2]
#define OFF_H     (OFF_BOUTP + 8)           // [64][68]
#define OFF_XS    (OFF_H + TB*HSTR)         // [8 warps][2][64]
#define SMEM_FLOATS (OFF_XS + NW*2*64)
#define SMEM_BYTES  (SMEM_FLOATS * sizeof(float))

typedef unsigned long long u64;

__device__ __forceinline__ u64 f2fma(u64 a, u64 b, u64 c) {
    u64 d;
    asm("fma.rn.f32x2 %0, %1, %2, %3;" : "=l"(d) : "l"(a), "l"(b), "l"(c));
    return d;
}
__device__ __forceinline__ u64 splat2(float v) {
    u64 d;
    asm("mov.b64 %0, {%1, %1};" : "=l"(d) : "f"(v));
    return d;
}
__device__ __forceinline__ void unpk(u64 v, float& a, float& b) {
    asm("mov.b64 {%0, %1}, %2;" : "=f"(a), "=f"(b) : "l"(v));
}
__device__ __forceinline__ u64 pack2(float a, float b) {
    u64 d;
    asm("mov.b64 %0, {%1, %2};" : "=l"(d) : "f"(a), "f"(b));
    return d;
}
__device__ __forceinline__ float tanha(float x) {
    float y;
    asm("tanh.approx.f32 %0, %1;" : "=f"(y) : "f"(x));
    return y;
}
__device__ __forceinline__ float sigt(float x) {          // sigmoid via HW tanh
    return fmaf(0.5f, tanha(0.5f * x), 0.5f);
}

// One GRU cell step for this warp's 8 rows x 64 units. Warp-private: no block sync.
__device__ __forceinline__ void gru_step(
    const float* __restrict__ wih,   // [8][192]  (k-major, gate*64+unit)
    const float* __restrict__ whh,   // [64][192]
    u64 br, u64 bz, u64 bni, u64 bnh,
    const float* __restrict__ xs,    // [8 rows][8 feats] staged x_t (warp-private)
    float* __restrict__ hwp,         // [8 rows][HSTR]    warp h base
    int lane2)
{
    u64 ar[RPW], az[RPW], an[RPW], ah[RPW];
    #pragma unroll
    for (int r = 0; r < RPW; r++) { ar[r] = br; az[r] = bz; an[r] = bni; ah[r] = bnh; }

    // ---- input GEMM: k = 0..7 ----
    #pragma unroll
    for (int k = 0; k < NF; k += 2) {
        float2 xv[RPW];
        #pragma unroll
        for (int r = 0; r < RPW; r++) xv[r] = *(const float2*)&xs[r * NF + k];
        #pragma unroll
        for (int kk = 0; kk < 2; kk++) {
            const float* w = wih + (k + kk) * G3 + lane2;
            u64 wr = *(const u64*)(w);
            u64 wz = *(const u64*)(w + 64);
            u64 wn = *(const u64*)(w + 128);
            #pragma unroll
            for (int r = 0; r < RPW; r++) {
                u64 hs = splat2(kk ? xv[r].y : xv[r].x);
                ar[r] = f2fma(hs, wr, ar[r]);
                az[r] = f2fma(hs, wz, az[r]);
                an[r] = f2fma(hs, wn, an[r]);
            }
        }
    }

    // ---- recurrent GEMM: k = 0..63 ----
    #pragma unroll 2
    for (int k = 0; k < HD; k += 2) {
        float2 hv[RPW];
        #pragma unroll
        for (int r = 0; r < RPW; r++) hv[r] = *(const float2*)&hwp[r * HSTR + k];
        #pragma unroll
        for (int kk = 0; kk < 2; kk++) {
            const float* w = whh + (k + kk) * G3 + lane2;
            u64 wr = *(const u64*)(w);
            u64 wz = *(const u64*)(w + 64);
            u64 wn = *(const u64*)(w + 128);
            #pragma unroll
            for (int r = 0; r < RPW; r++) {
                u64 hs = splat2(kk ? hv[r].y : hv[r].x);
                ar[r] = f2fma(hs, wr, ar[r]);
                az[r] = f2fma(hs, wz, az[r]);
                ah[r] = f2fma(hs, wn, ah[r]);
            }
        }
    }
    __syncwarp();

    // ---- gates + h update (lane owns units lane2, lane2+1) ----
    #pragma unroll
    for (int r = 0; r < RPW; r++) {
        float r0, r1, z0, z1, i0, i1, g0, g1;
        unpk(ar[r], r0, r1); unpk(az[r], z0, z1);
        unpk(an[r], i0, i1); unpk(ah[r], g0, g1);
        float R0 = sigt(r0), R1 = sigt(r1);
        float Z0 = sigt(z0), Z1 = sigt(z1);
        float N0 = tanha(fmaf(R0, g0, i0));
        float N1 = tanha(fmaf(R1, g1, i1));
        float2 ho = *(const float2*)&hwp[r * HSTR + lane2];
        float2 hn;
        hn.x = fmaf(Z0, ho.x - N0, N0);
        hn.y = fmaf(Z1, ho.y - N1, N1);
        *(float2*)&hwp[r * HSTR + lane2] = hn;
    }
    __syncwarp();
}

__global__ __launch_bounds__(NTHR, 1)
void seq2seq_gru_kernel(const float* __restrict__ x,
                        const float* __restrict__ xy,
                        const float* __restrict__ eWih, const float* __restrict__ eWhh,
                        const float* __restrict__ ebih, const float* __restrict__ ebhh,
                        const float* __restrict__ dWih, const float* __restrict__ dWhh,
                        const float* __restrict__ dbih, const float* __restrict__ dbhh,
                        const float* __restrict__ Wout, const float* __restrict__ bout,
                        float* __restrict__ out)
{
    extern __shared__ float smem[];
    float* ewih  = smem + OFF_EWIH;
    float* ewhh  = smem + OFF_EWHH;
    float* dwih  = smem + OFF_DWIH;
    float* dwhh  = smem + OFF_DWHH;
    float* ebias = smem + OFF_EB;
    float* dbias = smem + OFF_DB;
    float* woutp = smem + OFF_WOUTP;
    float* boutp = smem + OFF_BOUTP;
    float* hall  = smem + OFF_H;
    float* xsall = smem + OFF_XS;

    const int tid   = threadIdx.x;
    const int lane  = tid & 31;
    const int warp  = tid >> 5;
    const int lane2 = lane * 2;
    const int rowb  = blockIdx.x * TB + warp * RPW;   // this warp's first batch row

    float* hwp = hall + warp * RPW * HSTR;
    float* xsw = xsall + warp * 128;                  // two 64-float buffers

    // ---- cooperative init: weights (transposed to k-major), biases, zero h ----
    for (int i = tid; i < NF * G3; i += NTHR) {
        int k = i / G3, g = i % G3;
        ewih[i] = eWih[g * NF + k];
        dwih[i] = dWih[g * NF + k];
    }
    for (int i = tid; i < HD * G3; i += NTHR) {
        int k = i / G3, g = i % G3;
        ewhh[i] = eWhh[g * HD + k];
        dwhh[i] = dWhh[g * HD + k];
    }
    if (tid < HD) {
        ebias[tid]          = ebih[tid]        + ebhh[tid];
        ebias[64 + tid]     = ebih[64 + tid]   + ebhh[64 + tid];
        ebias[128 + tid]    = ebih[128 + tid];
        ebias[192 + tid]    = ebhh[128 + tid];
        dbias[tid]          = dbih[tid]        + dbhh[tid];
        dbias[64 + tid]     = dbih[64 + tid]   + dbhh[64 + tid];
        dbias[128 + tid]    = dbih[128 + tid];
        dbias[192 + tid]    = dbhh[128 + tid];
    }
    for (int i = tid; i < HD * 8; i += NTHR) {        // woutp[k][o4][s] = Wout[o4+4s][k]
        int k = i / 8, rem = i % 8, o4 = rem >> 1, s = rem & 1;
        woutp[i] = Wout[(o4 + 4 * s) * HD + k];
    }
    if (tid < 8) { int o4 = tid >> 1, s = tid & 1; boutp[tid] = bout[o4 + 4 * s]; }
    for (int i = tid; i < TB * HSTR; i += NTHR) hall[i] = 0.0f;
    __syncthreads();   // the ONLY block-wide sync

    // per-warp bias pairs
    u64 ebr  = *(const u64*)&ebias[lane2];
    u64 ebz  = *(const u64*)&ebias[64 + lane2];
    u64 ebni = *(const u64*)&ebias[128 + lane2];
    u64 ebnh = *(const u64*)&ebias[192 + lane2];

    // =========================== ENCODER ===========================
    {
        const float2* gx0 = (const float2*)x + ((size_t)0 * BATCH + rowb) * 4;
        float2 rx = gx0[lane];
        *(float2*)&xsw[lane2] = rx;                   // buffer 0
        __syncwarp();
        for (int t = 0; t < SEQ; t++) {
            if (t + 1 < SEQ) {
                const float2* gx = (const float2*)x + ((size_t)(t + 1) * BATCH + rowb) * 4;
                rx = gx[lane];
            }
            gru_step(ewih, ewhh, ebr, ebz, ebni, ebnh,
                     xsw + (t & 1) * 64, hwp, lane2);
            if (t + 1 < SEQ) {
                *(float2*)&xsw[((t + 1) & 1) * 64 + lane2] = rx;
            }
            __syncwarp();
        }
    }

    // =========================== DECODER ===========================
    u64 dbr  = *(const u64*)&dbias[lane2];
    u64 dbz  = *(const u64*)&dbias[64 + lane2];
    u64 dbni = *(const u64*)&dbias[128 + lane2];
    u64 dbnh = *(const u64*)&dbias[192 + lane2];

    const int orow = lane >> 2;            // out-proj: lane = orow*4 + o4
    const int oo4  = lane & 3;
    u64 bop = *(const u64*)&boutp[oo4 * 2];

    {
        const float2* gxy = (const float2*)xy + (size_t)rowb * 4;
        float2 rx = gxy[lane];
        *(float2*)&xsw[lane2] = rx;                   // buffer 0
        __syncwarp();

        for (int t = 0; t < LAB; t++) {
            gru_step(dwih, dwhh, dbr, dbz, dbni, dbnh,
                     xsw + (t & 1) * 64, hwp, lane2);

            // out = h_new @ Wout^T + bout  (pair of outputs o4, o4+4 per lane)
            u64 acc = bop;
            const float* hrow = hwp + orow * HSTR;
            #pragma unroll
            for (int k = 0; k < HD; k += 4) {
                float4 hh = *(const float4*)&hrow[k];
                u64 w0 = *(const u64*)&woutp[(k + 0) * 8 + oo4 * 2];
                u64 w1 = *(const u64*)&woutp[(k + 1) * 8 + oo4 * 2];
                u64 w2 = *(const u64*)&woutp[(k + 2) * 8 + oo4 * 2];
                u64 w3 = *(const u64*)&woutp[(k + 3) * 8 + oo4 * 2];
                acc = f2fma(splat2(hh.x), w0, acc);
                acc = f2fma(splat2(hh.y), w1, acc);
                acc = f2fma(splat2(hh.z), w2, acc);
                acc = f2fma(splat2(hh.w), w3, acc);
            }
            float oa, ob; unpk(acc, oa, ob);

            float* og = out + ((size_t)t * BATCH + rowb + orow) * NF;
            og[oo4]     = oa;
            og[oo4 + 4] = ob;

            if (t + 1 < LAB) {
                float* nb = xsw + ((t + 1) & 1) * 64 + orow * NF;
                nb[oo4]     = oa;
                nb[oo4 + 4] = ob;
            }
            __syncwarp();
        }
    }
}

extern "C" void kernel_launch(void* const* d_in, const int* in_sizes, int n_in,
                              void* d_out, int out_size) {
    (void)in_sizes; (void)n_in; (void)out_size;
    const float* x     = (const float*)d_in[0];
    const float* xy    = (const float*)d_in[1];
    const float* eWih  = (const float*)d_in[2];
    const float* eWhh  = (const float*)d_in[3];
    const float* ebih  = (const float*)d_in[4];
    const float* ebhh  = (const float*)d_in[5];
    const float* dWih  = (const float*)d_in[6];
    const float* dWhh  = (const float*)d_in[7];
    const float* dbih  = (const float*)d_in[8];
    const float* dbhh  = (const float*)d_in[9];
    const float* Wout  = (const float*)d_in[10];
    const float* bout  = (const float*)d_in[11];
    float* out = (float*)d_out;

    cudaFuncSetAttribute(seq2seq_gru_kernel,
                         cudaFuncAttributeMaxDynamicSharedMemorySize, SMEM_BYTES);
    seq2seq_gru_kernel<<<NBLK, NTHR, SMEM_BYTES>>>(
        x, xy, eWih, eWhh, ebih, ebhh, dWih, dWhh, dbih, dbhh, Wout, bout, out);
}